// round 3
// baseline (speedup 1.0000x reference)
#include <cuda_runtime.h>
#include <math.h>

// ---------------- problem constants ----------------
#define BZ    32
#define CH    19
#define NP    30
#define PS    200
#define S     (CH*NP)          // 570
#define T     (BZ*S)           // 18240
#define DM    200
#define LLM   4096
#define KC    4096
#define NCONV (BZ*25*S*8)      // 3,648,000
#define TPAD  18304            // 143 * 128
#define NOUT  (T*DM)           // 3,648,000
#define NCB   32               // KC/128 column blocks in score kernel

// ---------------- device scratch (bss, zero-init, no allocations) ----------------
__device__ float g_a[NCONV];
__device__ float g_b[NCONV];
__device__ float g_pe[NOUT];
__device__ float g_pe2[NOUT];
__device__ float g_proj[TPAD * LLM];     // rows >= T stay 0 (bss) forever
__device__ float g_table[KC * DM];
__device__ float g_cnorm[KC];
__device__ double g_cnorm_d[KC];
__device__ float g_stats[BZ * 5 * 2];
__device__ unsigned long long g_cand[(size_t)TPAD * NCB * 2];
__device__ int g_idx[T];

// ---------------- conv1: [32,1,570,200] -> [32,25,570,8], k=49, stride 25, pad 24 ----------------
__global__ void conv1_kernel(const float* __restrict__ x, const float* __restrict__ w,
                             const float* __restrict__ bias, float* __restrict__ out)
{
    int idx = blockIdx.x * blockDim.x + threadIdx.x;
    if (idx >= NCONV) return;
    int wo = idx & 7;
    int s  = (idx >> 3) % S;
    int c  = (idx / (S*8)) % 25;
    int b  = idx / (25*S*8);
    const float* xr = x + (b*S + s) * PS;
    const float* wr = w + c * 49;
    float acc = bias[c];
    int base = wo * 25 - 24;
    #pragma unroll
    for (int t = 0; t < 49; t++) {
        int n = base + t;
        if ((unsigned)n < (unsigned)PS) acc = fmaf(xr[n], wr[t], acc);
    }
    out[idx] = acc;
}

// ---------------- conv2/3: 25->25, k=(1,3), pad (0,1) ----------------
__global__ void conv25_kernel(const float* __restrict__ in, const float* __restrict__ w,
                              const float* __restrict__ bias, float* __restrict__ out)
{
    int idx = blockIdx.x * blockDim.x + threadIdx.x;
    if (idx >= NCONV) return;
    int wo = idx & 7;
    int s  = (idx >> 3) % S;
    int o  = (idx / (S*8)) % 25;
    int b  = idx / (25*S*8);
    const float* inb = in + (b*25*S + s) * 8 + wo;
    const float* wr  = w + o * 75;
    float acc = bias[o];
    #pragma unroll 5
    for (int i = 0; i < 25; i++) {
        const float* ir = inb + i * (S*8);
        float w0 = wr[i*3+0], w1 = wr[i*3+1], w2 = wr[i*3+2];
        if (wo > 0) acc = fmaf(ir[-1], w0, acc);
        acc = fmaf(ir[0], w1, acc);
        if (wo < 7) acc = fmaf(ir[1], w2, acc);
    }
    out[idx] = acc;
}

// ---------------- GroupNorm stats (fp64 accumulation): 160 groups of 22800 floats ---------
__global__ void gn_stats_kernel(const float* __restrict__ buf, float* __restrict__ stats)
{
    int grp = blockIdx.x;                 // b*5 + g
    const float* p = buf + grp * 22800;
    double s = 0.0, ss = 0.0;
    for (int i = threadIdx.x; i < 22800; i += 256) {
        double v = (double)p[i]; s += v; ss = fma(v, v, ss);
    }
    __shared__ double rs[256], rss[256];
    rs[threadIdx.x] = s; rss[threadIdx.x] = ss;
    __syncthreads();
    for (int o = 128; o; o >>= 1) {
        if (threadIdx.x < o) { rs[threadIdx.x] += rs[threadIdx.x+o]; rss[threadIdx.x] += rss[threadIdx.x+o]; }
        __syncthreads();
    }
    if (threadIdx.x == 0) {
        double mean = rs[0] * (1.0/22800.0);
        double var  = rss[0] * (1.0/22800.0) - mean*mean;
        stats[grp*2+0] = (float)mean;
        stats[grp*2+1] = (float)(1.0 / sqrt(var + 1e-5));
    }
}

// ---------------- GroupNorm apply + exact GELU (in-place) ----------------
__global__ void gn_apply_kernel(float* __restrict__ buf, const float* __restrict__ stats,
                                const float* __restrict__ gs, const float* __restrict__ gb)
{
    int idx = blockIdx.x * blockDim.x + threadIdx.x;
    if (idx >= NCONV) return;
    int c = (idx / (S*8)) % 25;
    int b = idx / (25*S*8);
    int grp = b*5 + c/5;
    float mean = stats[grp*2+0], rstd = stats[grp*2+1];
    float v = (buf[idx] - mean) * rstd * gs[c] + gb[c];
    buf[idx] = 0.5f * v * (1.0f + erff(v * 0.70710678118654752f));
}

// ---------------- spectral branch + transpose fuse ----------------
// pe[b,ci,pi,d] = h3[b, d/8, ci*30+pi, d%8] + spec_b[d] + sum_k |rfft(x)/200|[k] * spec_w[d,k]
__global__ void spec_kernel(const float* __restrict__ x, const float* __restrict__ h3,
                            const float* __restrict__ sw, const float* __restrict__ sb,
                            float* __restrict__ pe)
{
    __shared__ float xs[PS], ct[PS], st[PS], mag[101];
    int r = blockIdx.x;                   // 0 .. T-1
    int b = r / S, s = r % S;
    int tid = threadIdx.x;                // 128 threads
    for (int m = tid; m < PS; m += 128) {
        xs[m] = x[r*PS + m];
        float sv, cv;
        sincospif((float)m * 0.01f, &sv, &cv);   // angle = 2*pi*m/200
        ct[m] = cv; st[m] = sv;
    }
    __syncthreads();
    for (int k = tid; k <= 100; k += 128) {
        // 4 interleaved accumulators (pairwise-ish) to cut accumulation error ~2x
        float re0=0.f,re1=0.f,re2=0.f,re3=0.f;
        float im0=0.f,im1=0.f,im2=0.f,im3=0.f;
        int idx = 0;
        #pragma unroll 4
        for (int n = 0; n < PS; n += 4) {
            re0 = fmaf(xs[n+0], ct[idx], re0); im0 = fmaf(-xs[n+0], st[idx], im0);
            idx += k; if (idx >= PS) idx -= PS;
            re1 = fmaf(xs[n+1], ct[idx], re1); im1 = fmaf(-xs[n+1], st[idx], im1);
            idx += k; if (idx >= PS) idx -= PS;
            re2 = fmaf(xs[n+2], ct[idx], re2); im2 = fmaf(-xs[n+2], st[idx], im2);
            idx += k; if (idx >= PS) idx -= PS;
            re3 = fmaf(xs[n+3], ct[idx], re3); im3 = fmaf(-xs[n+3], st[idx], im3);
            idx += k; if (idx >= PS) idx -= PS;
        }
        float re = (re0+re1) + (re2+re3);
        float im = (im0+im1) + (im2+im3);
        mag[k] = sqrtf(re*re + im*im) * 0.005f;   // /200
    }
    __syncthreads();
    for (int d = tid; d < DM; d += 128) {
        const float* swr = sw + d * 101;
        float a0=0.f,a1=0.f,a2=0.f,a3=0.f;
        #pragma unroll 4
        for (int k = 0; k < 100; k += 4) {
            a0 = fmaf(mag[k+0], swr[k+0], a0);
            a1 = fmaf(mag[k+1], swr[k+1], a1);
            a2 = fmaf(mag[k+2], swr[k+2], a2);
            a3 = fmaf(mag[k+3], swr[k+3], a3);
        }
        float acc = sb[d] + ((a0+a1) + (a2+a3)) + mag[100]*swr[100];
        int c = d >> 3, w = d & 7;
        acc += h3[((b*25 + c)*S + s)*8 + w];
        pe[r*DM + d] = acc;
    }
}

// ---------------- depthwise positional conv 19x7, pad (9,3), + residual ----------------
__global__ void posconv_kernel(const float* __restrict__ pe, const float* __restrict__ pw,
                               const float* __restrict__ pb, float* __restrict__ out)
{
    int idx = blockIdx.x * blockDim.x + threadIdx.x;
    if (idx >= NOUT) return;
    int d  = idx % DM;
    int rp = idx / DM;
    int pi = rp % NP;
    int ci = (rp / NP) % CH;
    int b  = rp / S;
    float acc = pe[idx] + pb[d];
    const float* wr  = pw + d * (19*7);
    const float* peb = pe + (size_t)b * S * DM + d;
    for (int kh = 0; kh < 19; kh++) {
        int ih = ci + kh - 9;
        if ((unsigned)ih >= (unsigned)CH) continue;
        const float* row = peb + ih * NP * DM;
        #pragma unroll
        for (int kw = 0; kw < 7; kw++) {
            int iw = pi + kw - 3;
            if ((unsigned)iw >= (unsigned)NP) continue;
            acc = fmaf(row[iw * DM], wr[kh*7 + kw], acc);
        }
    }
    out[idx] = acc;
}

// ---------------- generic guarded NT GEMM: C[M,N] = A[M,K] * B[N,K]^T + bias[N] ----------------
__global__ void gemm_nt_kernel(const float* __restrict__ A, const float* __restrict__ B,
                               const float* __restrict__ bias, float* __restrict__ C,
                               int M, int N, int K)
{
    __shared__ float As[16][68];
    __shared__ float Bs[16][68];
    int t  = threadIdx.x;
    int tx = t & 15, ty = t >> 4;
    int bm0 = blockIdx.x * 64, bn0 = blockIdx.y * 64;
    float acc[4][4] = {};
    for (int k0 = 0; k0 < K; k0 += 16) {
        #pragma unroll
        for (int l = 0; l < 4; l++) {
            int e = t + 256*l;
            int row = e >> 4, kk = e & 15;
            int gk = k0 + kk;
            int gm = bm0 + row;
            int gn = bn0 + row;
            As[kk][row] = (gm < M && gk < K) ? A[(size_t)gm*K + gk] : 0.f;
            Bs[kk][row] = (gn < N && gk < K) ? B[(size_t)gn*K + gk] : 0.f;
        }
        __syncthreads();
        #pragma unroll
        for (int k = 0; k < 16; k++) {
            float a[4], bb[4];
            #pragma unroll
            for (int j = 0; j < 4; j++) a[j]  = As[k][ty*4+j];
            #pragma unroll
            for (int i = 0; i < 4; i++) bb[i] = Bs[k][tx*4+i];
            #pragma unroll
            for (int j = 0; j < 4; j++)
                #pragma unroll
                for (int i = 0; i < 4; i++)
                    acc[j][i] = fmaf(a[j], bb[i], acc[j][i]);
        }
        __syncthreads();
    }
    #pragma unroll
    for (int j = 0; j < 4; j++) {
        int m = bm0 + ty*4 + j;
        if (m >= M) continue;
        #pragma unroll
        for (int i = 0; i < 4; i++) {
            int n = bn0 + tx*4 + i;
            if (n < N) C[(size_t)m*N + n] = acc[j][i] + (bias ? bias[n] : 0.f);
        }
    }
}

// ---------------- 0.5 * ||codebook_k||^2 (fp64 accumulate; store fp32 + fp64) ----------------
__global__ void cnorm_kernel(const float* __restrict__ cb, float* __restrict__ cn,
                             double* __restrict__ cnd)
{
    int k = blockIdx.x;
    const float* p = cb + (size_t)k * LLM;
    double s = 0.0;
    for (int i = threadIdx.x; i < LLM; i += 256) { double v = (double)p[i]; s = fma(v, v, s); }
    __shared__ double rs[256];
    rs[threadIdx.x] = s; __syncthreads();
    for (int o = 128; o; o >>= 1) {
        if (threadIdx.x < o) rs[threadIdx.x] += rs[threadIdx.x+o];
        __syncthreads();
    }
    if (!threadIdx.x) { cn[k] = (float)(0.5 * rs[0]); cnd[k] = 0.5 * rs[0]; }
}

// ---------------- dominant kernel: scores = proj @ cb^T - cnorm, per-block top-2 ----------------
// M=TPAD (mult of 128), N=KC=4096, K=LLM=4096. No guards anywhere.
__global__ void __launch_bounds__(256, 2)
score_kernel(const float* __restrict__ A, const float* __restrict__ B,
             const float* __restrict__ cnorm, unsigned long long* __restrict__ cand)
{
    __shared__ float As[16][132];
    __shared__ float Bs[16][132];
    int t  = threadIdx.x;
    int tx = t & 15, ty = t >> 4;
    int bm0 = blockIdx.x * 128, bn0 = blockIdx.y * 128;

    int lrow = t >> 2;             // 0..63
    int lk4  = (t & 3) * 4;        // 0,4,8,12
    const float* Ap = A + (size_t)(bm0 + lrow) * LLM + lk4;
    const float* Bp = B + (size_t)(bn0 + lrow) * LLM + lk4;

    float acc[8][8] = {};
    float4 pa0 = *(const float4*)(Ap);
    float4 pa1 = *(const float4*)(Ap + (size_t)64 * LLM);
    float4 pb0 = *(const float4*)(Bp);
    float4 pb1 = *(const float4*)(Bp + (size_t)64 * LLM);

    for (int k0 = 0; k0 < LLM; k0 += 16) {
        As[lk4+0][lrow]    = pa0.x; As[lk4+1][lrow]    = pa0.y; As[lk4+2][lrow]    = pa0.z; As[lk4+3][lrow]    = pa0.w;
        As[lk4+0][lrow+64] = pa1.x; As[lk4+1][lrow+64] = pa1.y; As[lk4+2][lrow+64] = pa1.z; As[lk4+3][lrow+64] = pa1.w;
        Bs[lk4+0][lrow]    = pb0.x; Bs[lk4+1][lrow]    = pb0.y; Bs[lk4+2][lrow]    = pb0.z; Bs[lk4+3][lrow]    = pb0.w;
        Bs[lk4+0][lrow+64] = pb1.x; Bs[lk4+1][lrow+64] = pb1.y; Bs[lk4+2][lrow+64] = pb1.z; Bs[lk4+3][lrow+64] = pb1.w;
        __syncthreads();
        if (k0 + 16 < LLM) {
            pa0 = *(const float4*)(Ap + k0 + 16);
            pa1 = *(const float4*)(Ap + (size_t)64*LLM + k0 + 16);
            pb0 = *(const float4*)(Bp + k0 + 16);
            pb1 = *(const float4*)(Bp + (size_t)64*LLM + k0 + 16);
        }
        #pragma unroll
        for (int k = 0; k < 16; k++) {
            float a[8], bb[8];
            *(float4*)&a[0]  = *(const float4*)&As[k][ty*8];
            *(float4*)&a[4]  = *(const float4*)&As[k][ty*8+4];
            *(float4*)&bb[0] = *(const float4*)&Bs[k][tx*8];
            *(float4*)&bb[4] = *(const float4*)&Bs[k][tx*8+4];
            #pragma unroll
            for (int j = 0; j < 8; j++)
                #pragma unroll
                for (int i = 0; i < 8; i++)
                    acc[j][i] = fmaf(a[j], bb[i], acc[j][i]);
        }
        __syncthreads();
    }

    // epilogue: per-row top-2 within this 128-col block (score = acc - cnorm[col]);
    // packed key orders by score, tie -> smaller col (jnp.argmin semantics)
    float cn[8];
    #pragma unroll
    for (int i = 0; i < 8; i++) cn[i] = cnorm[bn0 + tx*8 + i];
    #pragma unroll
    for (int j = 0; j < 8; j++) {
        int row = bm0 + ty*8 + j;
        unsigned long long p1 = 0ull, p2 = 0ull;
        #pragma unroll
        for (int i = 0; i < 8; i++) {
            float sc = acc[j][i] - cn[i];
            int col = bn0 + tx*8 + i;
            unsigned int key = __float_as_uint(sc);
            key = (key & 0x80000000u) ? ~key : (key | 0x80000000u);
            unsigned long long p = ((unsigned long long)key << 32) | (unsigned int)(KC - 1 - col);
            if (p > p1) { p2 = p1; p1 = p; }
            else if (p > p2) { p2 = p; }
        }
        #pragma unroll
        for (int off = 8; off; off >>= 1) {
            unsigned long long q1 = __shfl_xor_sync(0xffffffffu, p1, off);
            unsigned long long q2 = __shfl_xor_sync(0xffffffffu, p2, off);
            if (q1 > p1) { p2 = (p1 > q2) ? p1 : q2; p1 = q1; }
            else if (q1 > p2) { p2 = q1; }
        }
        if (tx == 0) {
            size_t base = ((size_t)row * NCB + blockIdx.y) * 2;
            cand[base + 0] = p1;
            cand[base + 1] = p2;
        }
    }
}

// ---------------- refine: merge 64 candidates -> top-2, rescore both in fp64, pick winner ------
__global__ void refine_kernel(const unsigned long long* __restrict__ cand,
                              const float* __restrict__ A, const float* __restrict__ B,
                              const double* __restrict__ cnd, int* __restrict__ gidx)
{
    int row = blockIdx.x;                 // 0..T-1
    int tid = threadIdx.x;                // 128
    __shared__ int c1s, c2s;
    if (tid == 0) {
        unsigned long long p1 = 0ull, p2 = 0ull;
        const unsigned long long* pc = cand + (size_t)row * NCB * 2;
        #pragma unroll 8
        for (int i = 0; i < NCB*2; i++) {
            unsigned long long p = pc[i];
            if (p > p1) { p2 = p1; p1 = p; }
            else if (p > p2) { p2 = p; }
        }
        c1s = KC - 1 - (int)(unsigned int)(p1 & 0xffffffffull);
        c2s = KC - 1 - (int)(unsigned int)(p2 & 0xffffffffull);
    }
    __syncthreads();
    int ci = (tid < 64) ? c1s : c2s;
    const float* crow = B + (size_t)ci * LLM;
    const float* prow = A + (size_t)row * LLM;
    int lane = tid & 63;
    double s = 0.0;
    for (int i = lane; i < LLM; i += 64)
        s = fma((double)prow[i], (double)crow[i], s);
    __shared__ double red[128];
    red[tid] = s; __syncthreads();
    for (int o = 32; o; o >>= 1) {
        if ((tid & 63) < o) red[tid] += red[tid + o];
        __syncthreads();
    }
    if (tid == 0) {
        double s1 = red[0]  - cnd[c1s];
        double s2 = red[64] - cnd[c2s];
        int w;
        if (s1 > s2) w = c1s;
        else if (s2 > s1) w = c2s;
        else w = min(c1s, c2s);
        gidx[row] = w;
    }
}

// ---------------- gather: out[t,d] = table[idx_t, d] ----------------
__global__ void gather_kernel(const int* __restrict__ gidx,
                              const float* __restrict__ table, float* __restrict__ out)
{
    int idx = blockIdx.x * blockDim.x + threadIdx.x;
    if (idx >= NOUT) return;
    int t = idx / DM, d = idx % DM;
    int col = gidx[t];
    out[idx] = table[(size_t)col * DM + d];
}

// ---------------- host ----------------
extern "C" void kernel_launch(void* const* d_in, const int* in_sizes, int n_in,
                              void* d_out, int out_size)
{
    const float* x      = (const float*)d_in[0];
    const float* c1w    = (const float*)d_in[1];
    const float* c1b    = (const float*)d_in[2];
    const float* gn1s   = (const float*)d_in[3];
    const float* gn1b   = (const float*)d_in[4];
    const float* c2w    = (const float*)d_in[5];
    const float* c2b    = (const float*)d_in[6];
    const float* gn2s   = (const float*)d_in[7];
    const float* gn2b   = (const float*)d_in[8];
    const float* c3w    = (const float*)d_in[9];
    const float* c3b    = (const float*)d_in[10];
    const float* gn3s   = (const float*)d_in[11];
    const float* gn3b   = (const float*)d_in[12];
    const float* spec_w = (const float*)d_in[13];
    const float* spec_b = (const float*)d_in[14];
    const float* pos_w  = (const float*)d_in[15];
    const float* pos_b  = (const float*)d_in[16];
    const float* inp_w  = (const float*)d_in[17];
    const float* inp_b  = (const float*)d_in[18];
    const float* cb     = (const float*)d_in[19];
    const float* outp_w = (const float*)d_in[20];
    const float* outp_b = (const float*)d_in[21];
    float* out = (float*)d_out;

    float *pa, *pb, *ppe, *ppe2, *pproj, *ptable, *pcn, *pstats;
    double *pcnd;
    unsigned long long* pcand;
    int* pidx;
    cudaGetSymbolAddress((void**)&pa,     g_a);
    cudaGetSymbolAddress((void**)&pb,     g_b);
    cudaGetSymbolAddress((void**)&ppe,    g_pe);
    cudaGetSymbolAddress((void**)&ppe2,   g_pe2);
    cudaGetSymbolAddress((void**)&pproj,  g_proj);
    cudaGetSymbolAddress((void**)&ptable, g_table);
    cudaGetSymbolAddress((void**)&pcn,    g_cnorm);
    cudaGetSymbolAddress((void**)&pcnd,   g_cnorm_d);
    cudaGetSymbolAddress((void**)&pstats, g_stats);
    cudaGetSymbolAddress((void**)&pcand,  g_cand);
    cudaGetSymbolAddress((void**)&pidx,   g_idx);

    const int NB = (NCONV + 255) / 256;   // 14250

    // encoder chain
    conv1_kernel<<<NB, 256>>>(x, c1w, c1b, pa);
    gn_stats_kernel<<<160, 256>>>(pa, pstats);
    gn_apply_kernel<<<NB, 256>>>(pa, pstats, gn1s, gn1b);
    conv25_kernel<<<NB, 256>>>(pa, c2w, c2b, pb);
    gn_stats_kernel<<<160, 256>>>(pb, pstats);
    gn_apply_kernel<<<NB, 256>>>(pb, pstats, gn2s, gn2b);
    conv25_kernel<<<NB, 256>>>(pb, c3w, c3b, pa);
    gn_stats_kernel<<<160, 256>>>(pa, pstats);
    gn_apply_kernel<<<NB, 256>>>(pa, pstats, gn3s, gn3b);

    // spectral + transpose, positional conv
    spec_kernel<<<T, 128>>>(x, pa, spec_w, spec_b, ppe);
    posconv_kernel<<<NB, 256>>>(ppe, pos_w, pos_b, ppe2);

    // proj = pe2 @ inp_w^T + inp_b : [18240,200] x [4096,200]^T
    {
        dim3 grid(T/64, LLM/64);
        gemm_nt_kernel<<<grid, 256>>>(ppe2, inp_w, inp_b, pproj, T, LLM, DM);
    }
    // table = codebook @ outp_w^T + outp_b : [4096,4096] x [200,4096]^T
    {
        dim3 grid(KC/64, (DM + 63)/64);
        gemm_nt_kernel<<<grid, 256>>>(cb, outp_w, outp_b, ptable, KC, DM, LLM);
    }
    cnorm_kernel<<<KC, 256>>>(cb, pcn, pcnd);

    // dominant: fused score GEMM + per-block top-2
    {
        dim3 grid(TPAD/128, KC/128);
        score_kernel<<<grid, 256>>>(pproj, cb, pcn, pcand);
    }

    // exact (fp64) decision between global top-2 candidates
    refine_kernel<<<T, 128>>>(pcand, pproj, cb, pcnd, pidx);

    // gather quantized output
    gather_kernel<<<(NOUT + 255)/256, 256>>>(pidx, ptable, out);
}

// round 4
// speedup vs baseline: 2.0478x; 2.0478x over previous
#include <cuda_runtime.h>
#include <cuda_bf16.h>
#include <math.h>

// ---------------- problem constants ----------------
#define BZ    32
#define CH    19
#define NP    30
#define PS    200
#define S     (CH*NP)          // 570
#define T     (BZ*S)           // 18240
#define DM    200
#define LLM   4096
#define KC    4096
#define NCONV (BZ*25*S*8)      // 3,648,000
#define TPAD  18304            // 143 * 128
#define NOUT  (T*DM)           // 3,648,000
#define NCB64 64               // KC/64 column blocks (candidate granularity)

// ---------------- device scratch (bss, zero-init, no allocations) ----------------
__device__ float g_a[NCONV];
__device__ float g_b[NCONV];
__device__ float g_pe[NOUT];
__device__ float g_pe2[NOUT];
__device__ float g_proj[TPAD * LLM];            // rows >= T stay 0 (bss) forever
__device__ __nv_bfloat16 g_projh[TPAD * LLM];   // bf16 copy (rows >= T stay 0)
__device__ __nv_bfloat16 g_cbh[KC * LLM];       // bf16 codebook
__device__ float g_table[KC * DM];
__device__ float g_cnorm[KC];
__device__ double g_cnorm_d[KC];
__device__ float g_stats[BZ * 5 * 2];
__device__ unsigned long long g_cand[(size_t)TPAD * NCB64 * 2];
__device__ int g_idx[T];

// ---------------- conv1: [32,1,570,200] -> [32,25,570,8], k=49, stride 25, pad 24 ----------------
__global__ void conv1_kernel(const float* __restrict__ x, const float* __restrict__ w,
                             const float* __restrict__ bias, float* __restrict__ out)
{
    int idx = blockIdx.x * blockDim.x + threadIdx.x;
    if (idx >= NCONV) return;
    int wo = idx & 7;
    int s  = (idx >> 3) % S;
    int c  = (idx / (S*8)) % 25;
    int b  = idx / (25*S*8);
    const float* xr = x + (b*S + s) * PS;
    const float* wr = w + c * 49;
    float acc = bias[c];
    int base = wo * 25 - 24;
    #pragma unroll
    for (int t = 0; t < 49; t++) {
        int n = base + t;
        if ((unsigned)n < (unsigned)PS) acc = fmaf(xr[n], wr[t], acc);
    }
    out[idx] = acc;
}

// ---------------- conv2/3: 25->25, k=(1,3), pad (0,1) ----------------
__global__ void conv25_kernel(const float* __restrict__ in, const float* __restrict__ w,
                              const float* __restrict__ bias, float* __restrict__ out)
{
    int idx = blockIdx.x * blockDim.x + threadIdx.x;
    if (idx >= NCONV) return;
    int wo = idx & 7;
    int s  = (idx >> 3) % S;
    int o  = (idx / (S*8)) % 25;
    int b  = idx / (25*S*8);
    const float* inb = in + (b*25*S + s) * 8 + wo;
    const float* wr  = w + o * 75;
    float acc = bias[o];
    #pragma unroll 5
    for (int i = 0; i < 25; i++) {
        const float* ir = inb + i * (S*8);
        float w0 = wr[i*3+0], w1 = wr[i*3+1], w2 = wr[i*3+2];
        if (wo > 0) acc = fmaf(ir[-1], w0, acc);
        acc = fmaf(ir[0], w1, acc);
        if (wo < 7) acc = fmaf(ir[1], w2, acc);
    }
    out[idx] = acc;
}

// ---------------- GroupNorm stats (fp64 accumulation): 160 groups of 22800 floats ---------
__global__ void gn_stats_kernel(const float* __restrict__ buf, float* __restrict__ stats)
{
    int grp = blockIdx.x;                 // b*5 + g
    const float* p = buf + grp * 22800;
    double s = 0.0, ss = 0.0;
    for (int i = threadIdx.x; i < 22800; i += 256) {
        double v = (double)p[i]; s += v; ss = fma(v, v, ss);
    }
    __shared__ double rs[256], rss[256];
    rs[threadIdx.x] = s; rss[threadIdx.x] = ss;
    __syncthreads();
    for (int o = 128; o; o >>= 1) {
        if (threadIdx.x < o) { rs[threadIdx.x] += rs[threadIdx.x+o]; rss[threadIdx.x] += rss[threadIdx.x+o]; }
        __syncthreads();
    }
    if (threadIdx.x == 0) {
        double mean = rs[0] * (1.0/22800.0);
        double var  = rss[0] * (1.0/22800.0) - mean*mean;
        stats[grp*2+0] = (float)mean;
        stats[grp*2+1] = (float)(1.0 / sqrt(var + 1e-5));
    }
}

// ---------------- GroupNorm apply + exact GELU (in-place) ----------------
__global__ void gn_apply_kernel(float* __restrict__ buf, const float* __restrict__ stats,
                                const float* __restrict__ gs, const float* __restrict__ gb)
{
    int idx = blockIdx.x * blockDim.x + threadIdx.x;
    if (idx >= NCONV) return;
    int c = (idx / (S*8)) % 25;
    int b = idx / (25*S*8);
    int grp = b*5 + c/5;
    float mean = stats[grp*2+0], rstd = stats[grp*2+1];
    float v = (buf[idx] - mean) * rstd * gs[c] + gb[c];
    buf[idx] = 0.5f * v * (1.0f + erff(v * 0.70710678118654752f));
}

// ---------------- spectral branch + transpose fuse ----------------
__global__ void spec_kernel(const float* __restrict__ x, const float* __restrict__ h3,
                            const float* __restrict__ sw, const float* __restrict__ sb,
                            float* __restrict__ pe)
{
    __shared__ float xs[PS], ct[PS], st[PS], mag[101];
    int r = blockIdx.x;                   // 0 .. T-1
    int b = r / S, s = r % S;
    int tid = threadIdx.x;                // 128 threads
    for (int m = tid; m < PS; m += 128) {
        xs[m] = x[r*PS + m];
        float sv, cv;
        sincospif((float)m * 0.01f, &sv, &cv);
        ct[m] = cv; st[m] = sv;
    }
    __syncthreads();
    for (int k = tid; k <= 100; k += 128) {
        float re0=0.f,re1=0.f,re2=0.f,re3=0.f;
        float im0=0.f,im1=0.f,im2=0.f,im3=0.f;
        int idx = 0;
        #pragma unroll 4
        for (int n = 0; n < PS; n += 4) {
            re0 = fmaf(xs[n+0], ct[idx], re0); im0 = fmaf(-xs[n+0], st[idx], im0);
            idx += k; if (idx >= PS) idx -= PS;
            re1 = fmaf(xs[n+1], ct[idx], re1); im1 = fmaf(-xs[n+1], st[idx], im1);
            idx += k; if (idx >= PS) idx -= PS;
            re2 = fmaf(xs[n+2], ct[idx], re2); im2 = fmaf(-xs[n+2], st[idx], im2);
            idx += k; if (idx >= PS) idx -= PS;
            re3 = fmaf(xs[n+3], ct[idx], re3); im3 = fmaf(-xs[n+3], st[idx], im3);
            idx += k; if (idx >= PS) idx -= PS;
        }
        float re = (re0+re1) + (re2+re3);
        float im = (im0+im1) + (im2+im3);
        mag[k] = sqrtf(re*re + im*im) * 0.005f;
    }
    __syncthreads();
    for (int d = tid; d < DM; d += 128) {
        const float* swr = sw + d * 101;
        float a0=0.f,a1=0.f,a2=0.f,a3=0.f;
        #pragma unroll 4
        for (int k = 0; k < 100; k += 4) {
            a0 = fmaf(mag[k+0], swr[k+0], a0);
            a1 = fmaf(mag[k+1], swr[k+1], a1);
            a2 = fmaf(mag[k+2], swr[k+2], a2);
            a3 = fmaf(mag[k+3], swr[k+3], a3);
        }
        float acc = sb[d] + ((a0+a1) + (a2+a3)) + mag[100]*swr[100];
        int c = d >> 3, w = d & 7;
        acc += h3[((b*25 + c)*S + s)*8 + w];
        pe[r*DM + d] = acc;
    }
}

// ---------------- depthwise positional conv 19x7, pad (9,3), + residual ----------------
__global__ void posconv_kernel(const float* __restrict__ pe, const float* __restrict__ pw,
                               const float* __restrict__ pb, float* __restrict__ out)
{
    int idx = blockIdx.x * blockDim.x + threadIdx.x;
    if (idx >= NOUT) return;
    int d  = idx % DM;
    int rp = idx / DM;
    int pi = rp % NP;
    int ci = (rp / NP) % CH;
    int b  = rp / S;
    float acc = pe[idx] + pb[d];
    const float* wr  = pw + d * (19*7);
    const float* peb = pe + (size_t)b * S * DM + d;
    for (int kh = 0; kh < 19; kh++) {
        int ih = ci + kh - 9;
        if ((unsigned)ih >= (unsigned)CH) continue;
        const float* row = peb + ih * NP * DM;
        #pragma unroll
        for (int kw = 0; kw < 7; kw++) {
            int iw = pi + kw - 3;
            if ((unsigned)iw >= (unsigned)NP) continue;
            acc = fmaf(row[iw * DM], wr[kh*7 + kw], acc);
        }
    }
    out[idx] = acc;
}

// ---------------- generic guarded NT GEMM: C[M,N] = A[M,K] * B[N,K]^T + bias[N] ----------------
__global__ void gemm_nt_kernel(const float* __restrict__ A, const float* __restrict__ B,
                               const float* __restrict__ bias, float* __restrict__ C,
                               int M, int N, int K)
{
    __shared__ float As[16][68];
    __shared__ float Bs[16][68];
    int t  = threadIdx.x;
    int tx = t & 15, ty = t >> 4;
    int bm0 = blockIdx.x * 64, bn0 = blockIdx.y * 64;
    float acc[4][4] = {};
    for (int k0 = 0; k0 < K; k0 += 16) {
        #pragma unroll
        for (int l = 0; l < 4; l++) {
            int e = t + 256*l;
            int row = e >> 4, kk = e & 15;
            int gk = k0 + kk;
            int gm = bm0 + row;
            int gn = bn0 + row;
            As[kk][row] = (gm < M && gk < K) ? A[(size_t)gm*K + gk] : 0.f;
            Bs[kk][row] = (gn < N && gk < K) ? B[(size_t)gn*K + gk] : 0.f;
        }
        __syncthreads();
        #pragma unroll
        for (int k = 0; k < 16; k++) {
            float a[4], bb[4];
            #pragma unroll
            for (int j = 0; j < 4; j++) a[j]  = As[k][ty*4+j];
            #pragma unroll
            for (int i = 0; i < 4; i++) bb[i] = Bs[k][tx*4+i];
            #pragma unroll
            for (int j = 0; j < 4; j++)
                #pragma unroll
                for (int i = 0; i < 4; i++)
                    acc[j][i] = fmaf(a[j], bb[i], acc[j][i]);
        }
        __syncthreads();
    }
    #pragma unroll
    for (int j = 0; j < 4; j++) {
        int m = bm0 + ty*4 + j;
        if (m >= M) continue;
        #pragma unroll
        for (int i = 0; i < 4; i++) {
            int n = bn0 + tx*4 + i;
            if (n < N) C[(size_t)m*N + n] = acc[j][i] + (bias ? bias[n] : 0.f);
        }
    }
}

// ---------------- fp32 -> bf16 convert (n multiple of 4) ----------------
__global__ void cvt_bf16_kernel(const float* __restrict__ in, __nv_bfloat16* __restrict__ out,
                                size_t n4)
{
    size_t i = (size_t)blockIdx.x * blockDim.x + threadIdx.x;
    if (i >= n4) return;
    float4 v = ((const float4*)in)[i];
    __nv_bfloat162 lo = __nv_bfloat162(__float2bfloat16_rn(v.x), __float2bfloat16_rn(v.y));
    __nv_bfloat162 hi = __nv_bfloat162(__float2bfloat16_rn(v.z), __float2bfloat16_rn(v.w));
    ((__nv_bfloat162*)out)[2*i+0] = lo;
    ((__nv_bfloat162*)out)[2*i+1] = hi;
}

// ---------------- 0.5 * ||codebook_k||^2 (fp64 accumulate; store fp32 + fp64) ----------------
__global__ void cnorm_kernel(const float* __restrict__ cb, float* __restrict__ cn,
                             double* __restrict__ cnd)
{
    int k = blockIdx.x;
    const float* p = cb + (size_t)k * LLM;
    double s = 0.0;
    for (int i = threadIdx.x; i < LLM; i += 256) { double v = (double)p[i]; s = fma(v, v, s); }
    __shared__ double rs[256];
    rs[threadIdx.x] = s; __syncthreads();
    for (int o = 128; o; o >>= 1) {
        if (threadIdx.x < o) rs[threadIdx.x] += rs[threadIdx.x+o];
        __syncthreads();
    }
    if (!threadIdx.x) { cn[k] = (float)(0.5 * rs[0]); cnd[k] = 0.5 * rs[0]; }
}

// ---------------- dominant kernel: bf16 tensor-core coarse score GEMM, top-2 per 64-col block ----
// grid (KC/128=32, TPAD/128=143), 256 threads = 8 warps (4 m-rows x 2 n-cols of 32x64 warp tiles)
__global__ void __launch_bounds__(256)
score_bf16_kernel(const __nv_bfloat16* __restrict__ A, const __nv_bfloat16* __restrict__ B,
                  const float* __restrict__ cnorm, unsigned long long* __restrict__ cand)
{
    // smem tiles: 128 rows x 64 bf16, padded to 72 bf16 (144B, 16B-aligned) per row
    __shared__ __align__(16) char smA[128 * 144];
    __shared__ __align__(16) char smB[128 * 144];

    int t    = threadIdx.x;
    int lane = t & 31;
    int wid  = t >> 5;
    int gid  = lane >> 2;     // 0..7
    int tig  = lane & 3;      // 0..3
    int wm0  = (wid & 3) * 32;   // warp m offset within CTA tile
    int wn0  = (wid >> 2) * 64;  // warp n offset within CTA tile
    int bn0  = blockIdx.x * 128;
    int bm0  = blockIdx.y * 128;

    // global load mapping: chunk = 16B (8 bf16); 8 chunks/row; thread t -> rows rb+32i, col chunk cc
    int rb = t >> 3;          // 0..31
    int cc = t & 7;           // 0..7
    const char* gA = (const char*)(A + (size_t)(bm0 + rb) * LLM + cc * 8);
    const char* gB = (const char*)(B + (size_t)(bn0 + rb) * LLM + cc * 8);
    const size_t rowStride = (size_t)32 * LLM * 2;   // 32 rows in bytes

    float d[2][8][4] = {};    // [mi][j][{(g,2c),(g,2c+1),(g+8,2c),(g+8,2c+1)}]

    uint4 ra[4], rb4[4];
    #pragma unroll
    for (int i = 0; i < 4; i++) {
        ra[i]  = *(const uint4*)(gA + i * rowStride);
        rb4[i] = *(const uint4*)(gB + i * rowStride);
    }

    for (int k0 = 0; k0 < LLM; k0 += 64) {
        // store staged tile
        #pragma unroll
        for (int i = 0; i < 4; i++) {
            *(uint4*)(smA + (rb + 32*i) * 144 + cc * 16) = ra[i];
            *(uint4*)(smB + (rb + 32*i) * 144 + cc * 16) = rb4[i];
        }
        __syncthreads();
        if (k0 + 64 < LLM) {
            #pragma unroll
            for (int i = 0; i < 4; i++) {
                ra[i]  = *(const uint4*)(gA + i * rowStride + (k0 + 64) * 2);
                rb4[i] = *(const uint4*)(gB + i * rowStride + (k0 + 64) * 2);
            }
        }
        // compute 4 x k16 steps
        #pragma unroll
        for (int ks = 0; ks < 4; ks++) {
            unsigned int a[2][4];
            #pragma unroll
            for (int mi = 0; mi < 2; mi++) {
                int arow = wm0 + mi*16 + gid;
                const char* p = smA + arow * 144 + ks * 32 + tig * 4;
                a[mi][0] = *(const unsigned int*)(p);
                a[mi][1] = *(const unsigned int*)(p + 8*144);
                a[mi][2] = *(const unsigned int*)(p + 16);
                a[mi][3] = *(const unsigned int*)(p + 8*144 + 16);
            }
            #pragma unroll
            for (int j = 0; j < 8; j++) {
                int brow = wn0 + j*8 + gid;
                const char* p = smB + brow * 144 + ks * 32 + tig * 4;
                unsigned int b0 = *(const unsigned int*)(p);
                unsigned int b1 = *(const unsigned int*)(p + 16);
                #pragma unroll
                for (int mi = 0; mi < 2; mi++) {
                    asm volatile(
                        "mma.sync.aligned.m16n8k16.row.col.f32.bf16.bf16.f32 "
                        "{%0,%1,%2,%3},{%4,%5,%6,%7},{%8,%9},{%0,%1,%2,%3};"
                        : "+f"(d[mi][j][0]), "+f"(d[mi][j][1]), "+f"(d[mi][j][2]), "+f"(d[mi][j][3])
                        : "r"(a[mi][0]), "r"(a[mi][1]), "r"(a[mi][2]), "r"(a[mi][3]),
                          "r"(b0), "r"(b1));
                }
            }
        }
        __syncthreads();
    }

    // epilogue: per-row top-2 within this warp's 64-col slice
    float cn[8][2];
    #pragma unroll
    for (int j = 0; j < 8; j++) {
        cn[j][0] = cnorm[bn0 + wn0 + j*8 + tig*2 + 0];
        cn[j][1] = cnorm[bn0 + wn0 + j*8 + tig*2 + 1];
    }
    int cbi = blockIdx.x * 2 + (wid >> 2);   // 64-col block index, 0..63
    #pragma unroll
    for (int mi = 0; mi < 2; mi++) {
        #pragma unroll
        for (int h = 0; h < 2; h++) {
            int row = bm0 + wm0 + mi*16 + gid + h*8;
            unsigned long long p1 = 0ull, p2 = 0ull;
            #pragma unroll
            for (int j = 0; j < 8; j++) {
                #pragma unroll
                for (int c = 0; c < 2; c++) {
                    float sc = d[mi][j][h*2 + c] - cn[j][c];
                    int col = bn0 + wn0 + j*8 + tig*2 + c;
                    unsigned int key = __float_as_uint(sc);
                    key = (key & 0x80000000u) ? ~key : (key | 0x80000000u);
                    unsigned long long p = ((unsigned long long)key << 32) | (unsigned int)(KC - 1 - col);
                    if (p > p1) { p2 = p1; p1 = p; }
                    else if (p > p2) { p2 = p; }
                }
            }
            #pragma unroll
            for (int off = 1; off <= 2; off <<= 1) {
                unsigned long long q1 = __shfl_xor_sync(0xffffffffu, p1, off);
                unsigned long long q2 = __shfl_xor_sync(0xffffffffu, p2, off);
                if (q1 > p1) { p2 = (p1 > q2) ? p1 : q2; p1 = q1; }
                else if (q1 > p2) { p2 = q1; }
            }
            if (tig == 0) {
                size_t base = ((size_t)row * NCB64 + cbi) * 2;
                cand[base + 0] = p1;
                cand[base + 1] = p2;
            }
        }
    }
}

// ---------------- refine: merge 128 candidates -> top-8 (bf16 key), fp64 rescore, argmax ------
__global__ void refine8_kernel(const unsigned long long* __restrict__ cand,
                               const float* __restrict__ A, const float* __restrict__ B,
                               const double* __restrict__ cnd, int* __restrict__ gidx)
{
    int row  = blockIdx.x;                // 0..T-1
    int tid  = threadIdx.x;               // 256
    int lane = tid & 31, wid = tid >> 5;
    __shared__ int cidx[8];
    __shared__ double wsc[8];

    if (wid == 0) {
        unsigned long long v[4];
        const unsigned long long* pc = cand + (size_t)row * 128;
        #pragma unroll
        for (int i = 0; i < 4; i++) v[i] = pc[lane + 32*i];
        #pragma unroll
        for (int r = 0; r < 8; r++) {
            unsigned long long m = v[0];
            #pragma unroll
            for (int i = 1; i < 4; i++) if (v[i] > m) m = v[i];
            #pragma unroll
            for (int off = 16; off; off >>= 1) {
                unsigned long long q = __shfl_xor_sync(0xffffffffu, m, off);
                if (q > m) m = q;
            }
            // keys are unique (distinct cols) -> exactly one slot removed
            #pragma unroll
            for (int i = 0; i < 4; i++) if (v[i] == m) v[i] = 0ull;
            if (lane == 0) cidx[r] = KC - 1 - (int)(unsigned int)(m & 0xffffffffull);
        }
    }
    __syncthreads();

    int ci = cidx[wid];
    const float* crow = B + (size_t)ci * LLM;
    const float* prow = A + (size_t)row * LLM;
    double s = 0.0;
    for (int i = lane; i < LLM; i += 32)
        s = fma((double)prow[i], (double)crow[i], s);
    #pragma unroll
    for (int off = 16; off; off >>= 1)
        s += __shfl_xor_sync(0xffffffffu, s, off);
    if (lane == 0) wsc[wid] = s - cnd[ci];
    __syncthreads();

    if (tid == 0) {
        double bs = wsc[0]; int bi = cidx[0];
        #pragma unroll
        for (int w = 1; w < 8; w++) {
            if (wsc[w] > bs || (wsc[w] == bs && cidx[w] < bi)) { bs = wsc[w]; bi = cidx[w]; }
        }
        gidx[row] = bi;
    }
}

// ---------------- gather: out[t,d] = table[idx_t, d] ----------------
__global__ void gather_kernel(const int* __restrict__ gidx,
                              const float* __restrict__ table, float* __restrict__ out)
{
    int idx = blockIdx.x * blockDim.x + threadIdx.x;
    if (idx >= NOUT) return;
    int t = idx / DM, d = idx % DM;
    int col = gidx[t];
    out[idx] = table[(size_t)col * DM + d];
}

// ---------------- host ----------------
extern "C" void kernel_launch(void* const* d_in, const int* in_sizes, int n_in,
                              void* d_out, int out_size)
{
    const float* x      = (const float*)d_in[0];
    const float* c1w    = (const float*)d_in[1];
    const float* c1b    = (const float*)d_in[2];
    const float* gn1s   = (const float*)d_in[3];
    const float* gn1b   = (const float*)d_in[4];
    const float* c2w    = (const float*)d_in[5];
    const float* c2b    = (const float*)d_in[6];
    const float* gn2s   = (const float*)d_in[7];
    const float* gn2b   = (const float*)d_in[8];
    const float* c3w    = (const float*)d_in[9];
    const float* c3b    = (const float*)d_in[10];
    const float* gn3s   = (const float*)d_in[11];
    const float* gn3b   = (const float*)d_in[12];
    const float* spec_w = (const float*)d_in[13];
    const float* spec_b = (const float*)d_in[14];
    const float* pos_w  = (const float*)d_in[15];
    const float* pos_b  = (const float*)d_in[16];
    const float* inp_w  = (const float*)d_in[17];
    const float* inp_b  = (const float*)d_in[18];
    const float* cb     = (const float*)d_in[19];
    const float* outp_w = (const float*)d_in[20];
    const float* outp_b = (const float*)d_in[21];
    float* out = (float*)d_out;

    float *pa, *pb, *ppe, *ppe2, *pproj, *ptable, *pcn, *pstats;
    double *pcnd;
    __nv_bfloat16 *pprojh, *pcbh;
    unsigned long long* pcand;
    int* pidx;
    cudaGetSymbolAddress((void**)&pa,     g_a);
    cudaGetSymbolAddress((void**)&pb,     g_b);
    cudaGetSymbolAddress((void**)&ppe,    g_pe);
    cudaGetSymbolAddress((void**)&ppe2,   g_pe2);
    cudaGetSymbolAddress((void**)&pproj,  g_proj);
    cudaGetSymbolAddress((void**)&pprojh, g_projh);
    cudaGetSymbolAddress((void**)&pcbh,   g_cbh);
    cudaGetSymbolAddress((void**)&ptable, g_table);
    cudaGetSymbolAddress((void**)&pcn,    g_cnorm);
    cudaGetSymbolAddress((void**)&pcnd,   g_cnorm_d);
    cudaGetSymbolAddress((void**)&pstats, g_stats);
    cudaGetSymbolAddress((void**)&pcand,  g_cand);
    cudaGetSymbolAddress((void**)&pidx,   g_idx);

    const int NB = (NCONV + 255) / 256;   // 14250

    // encoder chain
    conv1_kernel<<<NB, 256>>>(x, c1w, c1b, pa);
    gn_stats_kernel<<<160, 256>>>(pa, pstats);
    gn_apply_kernel<<<NB, 256>>>(pa, pstats, gn1s, gn1b);
    conv25_kernel<<<NB, 256>>>(pa, c2w, c2b, pb);
    gn_stats_kernel<<<160, 256>>>(pb, pstats);
    gn_apply_kernel<<<NB, 256>>>(pb, pstats, gn2s, gn2b);
    conv25_kernel<<<NB, 256>>>(pb, c3w, c3b, pa);
    gn_stats_kernel<<<160, 256>>>(pa, pstats);
    gn_apply_kernel<<<NB, 256>>>(pa, pstats, gn3s, gn3b);

    // spectral + transpose, positional conv
    spec_kernel<<<T, 128>>>(x, pa, spec_w, spec_b, ppe);
    posconv_kernel<<<NB, 256>>>(ppe, pos_w, pos_b, ppe2);

    // proj = pe2 @ inp_w^T + inp_b : [18240,200] x [4096,200]^T (fp32, decision-grade)
    {
        dim3 grid(T/64, LLM/64);
        gemm_nt_kernel<<<grid, 256>>>(ppe2, inp_w, inp_b, pproj, T, LLM, DM);
    }
    // table = codebook @ outp_w^T + outp_b : [4096,4096] x [200,4096]^T
    {
        dim3 grid(KC/64, (DM + 63)/64);
        gemm_nt_kernel<<<grid, 256>>>(cb, outp_w, outp_b, ptable, KC, DM, LLM);
    }
    cnorm_kernel<<<KC, 256>>>(cb, pcn, pcnd);

    // bf16 copies for the tensor-core coarse pass
    {
        size_t n4p = (size_t)T * LLM / 4;
        cvt_bf16_kernel<<<(int)((n4p + 255)/256), 256>>>(pproj, pprojh, n4p);
        size_t n4c = (size_t)KC * LLM / 4;
        cvt_bf16_kernel<<<(int)((n4c + 255)/256), 256>>>(cb, pcbh, n4c);
    }

    // dominant: bf16 tensor-core score GEMM + per-64-col-block top-2 candidates
    {
        dim3 grid(KC/128, TPAD/128);
        score_bf16_kernel<<<grid, 256>>>(pprojh, pcbh, pcn, pcand);
    }

    // exact decision: top-8 by coarse key, fp64 rescore, argmax (tie -> smaller index)
    refine8_kernel<<<T, 256>>>(pcand, pproj, cb, pcnd, pidx);

    // gather quantized output
    gather_kernel<<<(NOUT + 255)/256, 256>>>(pidx, ptable, out);
}

// round 7
// speedup vs baseline: 2.1647x; 1.0571x over previous
#include <cuda_runtime.h>
#include <cuda_bf16.h>
#include <stdint.h>
#include <math.h>

// ---------------- problem constants ----------------
#define BZ    32
#define CH    19
#define NP    30
#define PS    200
#define S     (CH*NP)          // 570
#define T     (BZ*S)           // 18240
#define DM    200
#define LLM   4096
#define KC    4096
#define NCONV (BZ*25*S*8)      // 3,648,000
#define TPAD  18304            // 143 * 128
#define NOUT  (T*DM)           // 3,648,000
#define NCB32 128              // KC/32 column blocks (candidate granularity)

// ---------------- device scratch (bss, zero-init, no allocations) ----------------
__device__ float g_a[NCONV];
__device__ float g_b[NCONV];
__device__ float g_pe[NOUT];
__device__ float g_pe2[NOUT];
__device__ float g_proj[TPAD * LLM];            // rows >= T stay 0 (bss) forever
__device__ __nv_bfloat16 g_projh[TPAD * LLM];   // bf16 copy (rows >= T stay 0)
__device__ __nv_bfloat16 g_cbh[KC * LLM];       // bf16 codebook
__device__ float g_table[KC * DM];
__device__ float g_cnorm[KC];
__device__ double g_cnorm_d[KC];
__device__ float g_stats[BZ * 5 * 2];
__device__ unsigned long long g_cand[(size_t)TPAD * NCB32 * 2];
__device__ int g_idx[T];

// ---------------- conv1: [32,1,570,200] -> [32,25,570,8], k=49, stride 25, pad 24 ----------------
__global__ void conv1_kernel(const float* __restrict__ x, const float* __restrict__ w,
                             const float* __restrict__ bias, float* __restrict__ out)
{
    int idx = blockIdx.x * blockDim.x + threadIdx.x;
    if (idx >= NCONV) return;
    int wo = idx & 7;
    int s  = (idx >> 3) % S;
    int c  = (idx / (S*8)) % 25;
    int b  = idx / (25*S*8);
    const float* xr = x + (b*S + s) * PS;
    const float* wr = w + c * 49;
    float acc = bias[c];
    int base = wo * 25 - 24;
    #pragma unroll
    for (int t = 0; t < 49; t++) {
        int n = base + t;
        if ((unsigned)n < (unsigned)PS) acc = fmaf(xr[n], wr[t], acc);
    }
    out[idx] = acc;
}

// ---------------- conv2/3: 25->25, k=(1,3), pad (0,1) ----------------
__global__ void conv25_kernel(const float* __restrict__ in, const float* __restrict__ w,
                              const float* __restrict__ bias, float* __restrict__ out)
{
    int idx = blockIdx.x * blockDim.x + threadIdx.x;
    if (idx >= NCONV) return;
    int wo = idx & 7;
    int s  = (idx >> 3) % S;
    int o  = (idx / (S*8)) % 25;
    int b  = idx / (25*S*8);
    const float* inb = in + (b*25*S + s) * 8 + wo;
    const float* wr  = w + o * 75;
    float acc = bias[o];
    #pragma unroll 5
    for (int i = 0; i < 25; i++) {
        const float* ir = inb + i * (S*8);
        float w0 = wr[i*3+0], w1 = wr[i*3+1], w2 = wr[i*3+2];
        if (wo > 0) acc = fmaf(ir[-1], w0, acc);
        acc = fmaf(ir[0], w1, acc);
        if (wo < 7) acc = fmaf(ir[1], w2, acc);
    }
    out[idx] = acc;
}

// ---------------- GroupNorm stats (fp64 accumulation): 160 groups of 22800 floats ---------
__global__ void gn_stats_kernel(const float* __restrict__ buf, float* __restrict__ stats)
{
    int grp = blockIdx.x;                 // b*5 + g
    const float* p = buf + grp * 22800;
    double s = 0.0, ss = 0.0;
    for (int i = threadIdx.x; i < 22800; i += 256) {
        double v = (double)p[i]; s += v; ss = fma(v, v, ss);
    }
    __shared__ double rs[256], rss[256];
    rs[threadIdx.x] = s; rss[threadIdx.x] = ss;
    __syncthreads();
    for (int o = 128; o; o >>= 1) {
        if (threadIdx.x < o) { rs[threadIdx.x] += rs[threadIdx.x+o]; rss[threadIdx.x] += rss[threadIdx.x+o]; }
        __syncthreads();
    }
    if (threadIdx.x == 0) {
        double mean = rs[0] * (1.0/22800.0);
        double var  = rss[0] * (1.0/22800.0) - mean*mean;
        stats[grp*2+0] = (float)mean;
        stats[grp*2+1] = (float)(1.0 / sqrt(var + 1e-5));
    }
}

// ---------------- GroupNorm apply + exact GELU (in-place) ----------------
__global__ void gn_apply_kernel(float* __restrict__ buf, const float* __restrict__ stats,
                                const float* __restrict__ gs, const float* __restrict__ gb)
{
    int idx = blockIdx.x * blockDim.x + threadIdx.x;
    if (idx >= NCONV) return;
    int c = (idx / (S*8)) % 25;
    int b = idx / (25*S*8);
    int grp = b*5 + c/5;
    float mean = stats[grp*2+0], rstd = stats[grp*2+1];
    float v = (buf[idx] - mean) * rstd * gs[c] + gb[c];
    buf[idx] = 0.5f * v * (1.0f + erff(v * 0.70710678118654752f));
}

// ---------------- spectral branch + transpose fuse ----------------
__global__ void spec_kernel(const float* __restrict__ x, const float* __restrict__ h3,
                            const float* __restrict__ sw, const float* __restrict__ sb,
                            float* __restrict__ pe)
{
    __shared__ float xs[PS], ct[PS], st[PS], mag[101];
    int r = blockIdx.x;                   // 0 .. T-1
    int b = r / S, s = r % S;
    int tid = threadIdx.x;                // 128 threads
    for (int m = tid; m < PS; m += 128) {
        xs[m] = x[r*PS + m];
        float sv, cv;
        sincospif((float)m * 0.01f, &sv, &cv);
        ct[m] = cv; st[m] = sv;
    }
    __syncthreads();
    for (int k = tid; k <= 100; k += 128) {
        float re0=0.f,re1=0.f,re2=0.f,re3=0.f;
        float im0=0.f,im1=0.f,im2=0.f,im3=0.f;
        int idx = 0;
        #pragma unroll 4
        for (int n = 0; n < PS; n += 4) {
            re0 = fmaf(xs[n+0], ct[idx], re0); im0 = fmaf(-xs[n+0], st[idx], im0);
            idx += k; if (idx >= PS) idx -= PS;
            re1 = fmaf(xs[n+1], ct[idx], re1); im1 = fmaf(-xs[n+1], st[idx], im1);
            idx += k; if (idx >= PS) idx -= PS;
            re2 = fmaf(xs[n+2], ct[idx], re2); im2 = fmaf(-xs[n+2], st[idx], im2);
            idx += k; if (idx >= PS) idx -= PS;
            re3 = fmaf(xs[n+3], ct[idx], re3); im3 = fmaf(-xs[n+3], st[idx], im3);
            idx += k; if (idx >= PS) idx -= PS;
        }
        float re = (re0+re1) + (re2+re3);
        float im = (im0+im1) + (im2+im3);
        mag[k] = sqrtf(re*re + im*im) * 0.005f;
    }
    __syncthreads();
    for (int d = tid; d < DM; d += 128) {
        const float* swr = sw + d * 101;
        float a0=0.f,a1=0.f,a2=0.f,a3=0.f;
        #pragma unroll 4
        for (int k = 0; k < 100; k += 4) {
            a0 = fmaf(mag[k+0], swr[k+0], a0);
            a1 = fmaf(mag[k+1], swr[k+1], a1);
            a2 = fmaf(mag[k+2], swr[k+2], a2);
            a3 = fmaf(mag[k+3], swr[k+3], a3);
        }
        float acc = sb[d] + ((a0+a1) + (a2+a3)) + mag[100]*swr[100];
        int c = d >> 3, w = d & 7;
        acc += h3[((b*25 + c)*S + s)*8 + w];
        pe[r*DM + d] = acc;
    }
}

// ---------------- depthwise positional conv 19x7, pad (9,3), + residual ----------------
__global__ void posconv_kernel(const float* __restrict__ pe, const float* __restrict__ pw,
                               const float* __restrict__ pb, float* __restrict__ out)
{
    int idx = blockIdx.x * blockDim.x + threadIdx.x;
    if (idx >= NOUT) return;
    int d  = idx % DM;
    int rp = idx / DM;
    int pi = rp % NP;
    int ci = (rp / NP) % CH;
    int b  = rp / S;
    float acc = pe[idx] + pb[d];
    const float* wr  = pw + d * (19*7);
    const float* peb = pe + (size_t)b * S * DM + d;
    for (int kh = 0; kh < 19; kh++) {
        int ih = ci + kh - 9;
        if ((unsigned)ih >= (unsigned)CH) continue;
        const float* row = peb + ih * NP * DM;
        #pragma unroll
        for (int kw = 0; kw < 7; kw++) {
            int iw = pi + kw - 3;
            if ((unsigned)iw >= (unsigned)NP) continue;
            acc = fmaf(row[iw * DM], wr[kh*7 + kw], acc);
        }
    }
    out[idx] = acc;
}

// ---------------- generic guarded NT GEMM: C[M,N] = A[M,K] * B[N,K]^T + bias[N] ----------------
__global__ void gemm_nt_kernel(const float* __restrict__ A, const float* __restrict__ B,
                               const float* __restrict__ bias, float* __restrict__ C,
                               int M, int N, int K)
{
    __shared__ float As[16][68];
    __shared__ float Bs[16][68];
    int t  = threadIdx.x;
    int tx = t & 15, ty = t >> 4;
    int bm0 = blockIdx.x * 64, bn0 = blockIdx.y * 64;
    float acc[4][4] = {};
    for (int k0 = 0; k0 < K; k0 += 16) {
        #pragma unroll
        for (int l = 0; l < 4; l++) {
            int e = t + 256*l;
            int row = e >> 4, kk = e & 15;
            int gk = k0 + kk;
            int gm = bm0 + row;
            int gn = bn0 + row;
            As[kk][row] = (gm < M && gk < K) ? A[(size_t)gm*K + gk] : 0.f;
            Bs[kk][row] = (gn < N && gk < K) ? B[(size_t)gn*K + gk] : 0.f;
        }
        __syncthreads();
        #pragma unroll
        for (int k = 0; k < 16; k++) {
            float a[4], bb[4];
            #pragma unroll
            for (int j = 0; j < 4; j++) a[j]  = As[k][ty*4+j];
            #pragma unroll
            for (int i = 0; i < 4; i++) bb[i] = Bs[k][tx*4+i];
            #pragma unroll
            for (int j = 0; j < 4; j++)
                #pragma unroll
                for (int i = 0; i < 4; i++)
                    acc[j][i] = fmaf(a[j], bb[i], acc[j][i]);
        }
        __syncthreads();
    }
    #pragma unroll
    for (int j = 0; j < 4; j++) {
        int m = bm0 + ty*4 + j;
        if (m >= M) continue;
        #pragma unroll
        for (int i = 0; i < 4; i++) {
            int n = bn0 + tx*4 + i;
            if (n < N) C[(size_t)m*N + n] = acc[j][i] + (bias ? bias[n] : 0.f);
        }
    }
}

// ---------------- fp32 -> bf16 convert (n multiple of 4) ----------------
__global__ void cvt_bf16_kernel(const float* __restrict__ in, __nv_bfloat16* __restrict__ out,
                                size_t n4)
{
    size_t i = (size_t)blockIdx.x * blockDim.x + threadIdx.x;
    if (i >= n4) return;
    float4 v = ((const float4*)in)[i];
    __nv_bfloat162 lo = __nv_bfloat162(__float2bfloat16_rn(v.x), __float2bfloat16_rn(v.y));
    __nv_bfloat162 hi = __nv_bfloat162(__float2bfloat16_rn(v.z), __float2bfloat16_rn(v.w));
    ((__nv_bfloat162*)out)[2*i+0] = lo;
    ((__nv_bfloat162*)out)[2*i+1] = hi;
}

// ---------------- 0.5 * ||codebook_k||^2 (fp64 accumulate; store fp32 + fp64) ----------------
__global__ void cnorm_kernel(const float* __restrict__ cb, float* __restrict__ cn,
                             double* __restrict__ cnd)
{
    int k = blockIdx.x;
    const float* p = cb + (size_t)k * LLM;
    double s = 0.0;
    for (int i = threadIdx.x; i < LLM; i += 256) { double v = (double)p[i]; s = fma(v, v, s); }
    __shared__ double rs[256];
    rs[threadIdx.x] = s; __syncthreads();
    for (int o = 128; o; o >>= 1) {
        if (threadIdx.x < o) rs[threadIdx.x] += rs[threadIdx.x+o];
        __syncthreads();
    }
    if (!threadIdx.x) { cn[k] = (float)(0.5 * rs[0]); cnd[k] = 0.5 * rs[0]; }
}

// =====================================================================================
// mma.sync bf16 score GEMM, pipelined:
//   CTA tile 128x128, 8 warps (warp tile 64x32), K chunk 64, cp.async 3-slot ring
//   (stage distance 2, one __syncthreads per chunk), ldmatrix.x4 fragment loads,
//   128B-swizzled smem. Epilogue: per-row top-2 per 32-col block from fragments.
// =====================================================================================

// dynamic smem: A slots [0,49152), B slots [49152,98304), cnorm [98304,98816)
#define SM_SLOT   16384
#define SM_BOFF   49152
#define SM_CN     98304
#define SM_TOTAL  (98304 + 512 + 128)

__device__ __forceinline__ uint32_t smem_u32(const void* p) {
    uint32_t a;
    asm("{ .reg .u64 t; cvta.to.shared.u64 t, %1; cvt.u32.u64 %0, t; }" : "=r"(a) : "l"(p));
    return a;
}

__device__ __forceinline__ void ldsm4(uint32_t* r, uint32_t addr) {
    asm volatile("ldmatrix.sync.aligned.m8n8.x4.shared.b16 {%0,%1,%2,%3}, [%4];"
        : "=r"(r[0]), "=r"(r[1]), "=r"(r[2]), "=r"(r[3]) : "r"(addr));
}

__device__ __forceinline__ void mma16816(float* d, const uint32_t* a, uint32_t b0, uint32_t b1) {
    asm volatile("mma.sync.aligned.m16n8k16.row.col.f32.bf16.bf16.f32 "
        "{%0,%1,%2,%3},{%4,%5,%6,%7},{%8,%9},{%0,%1,%2,%3};"
        : "+f"(d[0]), "+f"(d[1]), "+f"(d[2]), "+f"(d[3])
        : "r"(a[0]), "r"(a[1]), "r"(a[2]), "r"(a[3]), "r"(b0), "r"(b1));
}

__device__ __forceinline__ void sc_stage(const __nv_bfloat16* __restrict__ A,
                                         const __nv_bfloat16* __restrict__ B,
                                         uint32_t sb, int bm0, int bn0, int c, int tid)
{
    int slot = c % 3;
    uint32_t dA = sb + slot * SM_SLOT;
    uint32_t dB = sb + SM_BOFF + slot * SM_SLOT;
    size_t koff = (size_t)c * 64;
    #pragma unroll
    for (int j = 0; j < 4; j++) {
        int idx = tid + j * 256;               // 0..1023
        int row = idx >> 3, ch = idx & 7;
        uint32_t so = (uint32_t)(row * 128 + ((ch ^ (row & 7)) << 4));
        const void* sA = (const void*)(A + (size_t)(bm0 + row) * LLM + koff + ch * 8);
        const void* sB = (const void*)(B + (size_t)(bn0 + row) * LLM + koff + ch * 8);
        asm volatile("cp.async.cg.shared.global [%0], [%1], 16;" :: "r"(dA + so), "l"(sA));
        asm volatile("cp.async.cg.shared.global [%0], [%1], 16;" :: "r"(dB + so), "l"(sB));
    }
    asm volatile("cp.async.commit_group;" ::: "memory");
}

__global__ void __launch_bounds__(256)
score_mma_kernel(const __nv_bfloat16* __restrict__ A, const __nv_bfloat16* __restrict__ B,
                 const float* __restrict__ cnorm, unsigned long long* __restrict__ cand)
{
    extern __shared__ __align__(128) char smem[];
    uint32_t sb = smem_u32(smem);
    int tid = threadIdx.x, lane = tid & 31, wid = tid >> 5;
    int bn0 = blockIdx.x * 128, bm0 = blockIdx.y * 128;
    int wm0 = (wid & 1) * 64, wn0 = (wid >> 1) * 32;

    float* scn = (float*)(smem + SM_CN);
    if (tid < 128) scn[tid] = cnorm[bn0 + tid];

    // ldmatrix per-thread offsets
    int lr16 = lane & 15, lcA = lane >> 4;      // A: rows-in-16, chunk half
    int lr8  = lane & 7,  lcB = lane >> 3;      // B: rows-in-8, chunk quarter
    uint32_t offA[4], offB[2];
    #pragma unroll
    for (int q = 0; q < 4; q++)                 // k16 step q -> chunk base 2q
        offA[q] = (uint32_t)((wm0 + lr16) * 128 + (((2*q + lcA) ^ (lr16 & 7)) << 4));
    #pragma unroll
    for (int s = 0; s < 2; s++)                 // k32 step s -> chunk base 4s
        offB[s] = (uint32_t)((wn0 + lr8) * 128 + (((4*s + lcB) ^ lr8) << 4));

    float acc[4][4][4] = {};                    // [mi][j][reg]

    sc_stage(A, B, sb, bm0, bn0, 0, tid);
    sc_stage(A, B, sb, bm0, bn0, 1, tid);

    for (int c = 0; c < 64; c++) {
        if (c < 62) { asm volatile("cp.async.wait_group 1;" ::: "memory"); }
        else        { asm volatile("cp.async.wait_group 0;" ::: "memory"); }
        __syncthreads();                         // chunk c resident in slot c%3
        if (c + 2 < 64) sc_stage(A, B, sb, bm0, bn0, c + 2, tid);   // slot (c-1)%3, freed

        uint32_t aBase = sb + (c % 3) * SM_SLOT;
        uint32_t bBase = sb + SM_BOFF + (c % 3) * SM_SLOT;
        #pragma unroll
        for (int s = 0; s < 2; s++) {
            uint32_t bq[4][4];
            #pragma unroll
            for (int j = 0; j < 4; j++)
                ldsm4(bq[j], bBase + j * 1024 + offB[s]);
            #pragma unroll
            for (int h = 0; h < 2; h++) {
                uint32_t aq[4][4];
                #pragma unroll
                for (int mi = 0; mi < 4; mi++)
                    ldsm4(aq[mi], aBase + mi * 2048 + offA[s*2 + h]);
                #pragma unroll
                for (int j = 0; j < 4; j++)
                    #pragma unroll
                    for (int mi = 0; mi < 4; mi++)
                        mma16816(acc[mi][j], aq[mi], bq[j][2*h], bq[j][2*h+1]);
            }
        }
    }

    // epilogue: per-row top-2 within this warp's 32-col slice
    int g = lane >> 2, tq = lane & 3;
    int cb = blockIdx.x * 4 + (wid >> 1);        // 32-col block index, 0..127
    #pragma unroll
    for (int mi = 0; mi < 4; mi++) {
        #pragma unroll
        for (int h2 = 0; h2 < 2; h2++) {
            int row = bm0 + wm0 + mi*16 + h2*8 + g;
            unsigned long long p1 = 0ull, p2 = 0ull;
            #pragma unroll
            for (int j = 0; j < 4; j++) {
                #pragma unroll
                for (int e = 0; e < 2; e++) {
                    int colL = wn0 + j*8 + tq*2 + e;
                    float sc = acc[mi][j][h2*2 + e] - scn[colL];
                    int col = bn0 + colL;
                    unsigned int key = __float_as_uint(sc);
                    key = (key & 0x80000000u) ? ~key : (key | 0x80000000u);
                    unsigned long long p =
                        ((unsigned long long)key << 32) | (unsigned int)(KC - 1 - col);
                    if (p > p1) { p2 = p1; p1 = p; }
                    else if (p > p2) { p2 = p; }
                }
            }
            #pragma unroll
            for (int off = 1; off <= 2; off <<= 1) {
                unsigned long long q1 = __shfl_xor_sync(0xffffffffu, p1, off);
                unsigned long long q2 = __shfl_xor_sync(0xffffffffu, p2, off);
                if (q1 > p1) { p2 = (p1 > q2) ? p1 : q2; p1 = q1; }
                else if (q1 > p2) { p2 = q1; }
            }
            if (tq == 0) {
                size_t base = ((size_t)row * NCB32 + cb) * 2;
                cand[base + 0] = p1;
                cand[base + 1] = p2;
            }
        }
    }
}

// ---------------- refine: merge 256 candidates -> top-8, fp64 rescore, argmax ----------------
__global__ void refine8_kernel(const unsigned long long* __restrict__ cand,
                               const float* __restrict__ A, const float* __restrict__ B,
                               const double* __restrict__ cnd, int* __restrict__ gidx)
{
    int row  = blockIdx.x;                // 0..T-1
    int tid  = threadIdx.x;               // 256
    int lane = tid & 31, wid = tid >> 5;
    __shared__ int cidx[8];
    __shared__ double wsc[8];

    if (wid == 0) {
        unsigned long long v[8];
        const unsigned long long* pc = cand + (size_t)row * (NCB32 * 2);
        #pragma unroll
        for (int i = 0; i < 8; i++) v[i] = pc[lane + 32*i];
        #pragma unroll
        for (int r = 0; r < 8; r++) {
            unsigned long long m = v[0];
            #pragma unroll
            for (int i = 1; i < 8; i++) if (v[i] > m) m = v[i];
            #pragma unroll
            for (int off = 16; off; off >>= 1) {
                unsigned long long q = __shfl_xor_sync(0xffffffffu, m, off);
                if (q > m) m = q;
            }
            #pragma unroll
            for (int i = 0; i < 8; i++) if (v[i] == m) v[i] = 0ull;
            if (lane == 0) cidx[r] = KC - 1 - (int)(unsigned int)(m & 0xffffffffull);
        }
    }
    __syncthreads();

    int ci = cidx[wid];
    const float* crow = B + (size_t)ci * LLM;
    const float* prow = A + (size_t)row * LLM;
    double s = 0.0;
    for (int i = lane; i < LLM; i += 32)
        s = fma((double)prow[i], (double)crow[i], s);
    #pragma unroll
    for (int off = 16; off; off >>= 1)
        s += __shfl_xor_sync(0xffffffffu, s, off);
    if (lane == 0) wsc[wid] = s - cnd[ci];
    __syncthreads();

    if (tid == 0) {
        double bs = wsc[0]; int bi = cidx[0];
        #pragma unroll
        for (int w = 1; w < 8; w++) {
            if (wsc[w] > bs || (wsc[w] == bs && cidx[w] < bi)) { bs = wsc[w]; bi = cidx[w]; }
        }
        gidx[row] = bi;
    }
}

// ---------------- gather: out[t,d] = table[idx_t, d] ----------------
__global__ void gather_kernel(const int* __restrict__ gidx,
                              const float* __restrict__ table, float* __restrict__ out)
{
    int idx = blockIdx.x * blockDim.x + threadIdx.x;
    if (idx >= NOUT) return;
    int t = idx / DM, d = idx % DM;
    int col = gidx[t];
    out[idx] = table[(size_t)col * DM + d];
}

// ---------------- host ----------------
extern "C" void kernel_launch(void* const* d_in, const int* in_sizes, int n_in,
                              void* d_out, int out_size)
{
    const float* x      = (const float*)d_in[0];
    const float* c1w    = (const float*)d_in[1];
    const float* c1b    = (const float*)d_in[2];
    const float* gn1s   = (const float*)d_in[3];
    const float* gn1b   = (const float*)d_in[4];
    const float* c2w    = (const float*)d_in[5];
    const float* c2b    = (const float*)d_in[6];
    const float* gn2s   = (const float*)d_in[7];
    const float* gn2b   = (const float*)d_in[8];
    const float* c3w    = (const float*)d_in[9];
    const float* c3b    = (const float*)d_in[10];
    const float* gn3s   = (const float*)d_in[11];
    const float* gn3b   = (const float*)d_in[12];
    const float* spec_w = (const float*)d_in[13];
    const float* spec_b = (const float*)d_in[14];
    const float* pos_w  = (const float*)d_in[15];
    const float* pos_b  = (const float*)d_in[16];
    const float* inp_w  = (const float*)d_in[17];
    const float* inp_b  = (const float*)d_in[18];
    const float* cb     = (const float*)d_in[19];
    const float* outp_w = (const float*)d_in[20];
    const float* outp_b = (const float*)d_in[21];
    float* out = (float*)d_out;

    float *pa, *pb, *ppe, *ppe2, *pproj, *ptable, *pcn, *pstats;
    double *pcnd;
    __nv_bfloat16 *pprojh, *pcbh;
    unsigned long long* pcand;
    int* pidx;
    cudaGetSymbolAddress((void**)&pa,     g_a);
    cudaGetSymbolAddress((void**)&pb,     g_b);
    cudaGetSymbolAddress((void**)&ppe,    g_pe);
    cudaGetSymbolAddress((void**)&ppe2,   g_pe2);
    cudaGetSymbolAddress((void**)&pproj,  g_proj);
    cudaGetSymbolAddress((void**)&pprojh, g_projh);
    cudaGetSymbolAddress((void**)&pcbh,   g_cbh);
    cudaGetSymbolAddress((void**)&ptable, g_table);
    cudaGetSymbolAddress((void**)&pcn,    g_cnorm);
    cudaGetSymbolAddress((void**)&pcnd,   g_cnorm_d);
    cudaGetSymbolAddress((void**)&pstats, g_stats);
    cudaGetSymbolAddress((void**)&pcand,  g_cand);
    cudaGetSymbolAddress((void**)&pidx,   g_idx);

    cudaFuncSetAttribute(score_mma_kernel,
                         cudaFuncAttributeMaxDynamicSharedMemorySize, SM_TOTAL);

    const int NB = (NCONV + 255) / 256;   // 14250

    // encoder chain
    conv1_kernel<<<NB, 256>>>(x, c1w, c1b, pa);
    gn_stats_kernel<<<160, 256>>>(pa, pstats);
    gn_apply_kernel<<<NB, 256>>>(pa, pstats, gn1s, gn1b);
    conv25_kernel<<<NB, 256>>>(pa, c2w, c2b, pb);
    gn_stats_kernel<<<160, 256>>>(pb, pstats);
    gn_apply_kernel<<<NB, 256>>>(pb, pstats, gn2s, gn2b);
    conv25_kernel<<<NB, 256>>>(pb, c3w, c3b, pa);
    gn_stats_kernel<<<160, 256>>>(pa, pstats);
    gn_apply_kernel<<<NB, 256>>>(pa, pstats, gn3s, gn3b);

    // spectral + transpose, positional conv
    spec_kernel<<<T, 128>>>(x, pa, spec_w, spec_b, ppe);
    posconv_kernel<<<NB, 256>>>(ppe, pos_w, pos_b, ppe2);

    // proj = pe2 @ inp_w^T + inp_b : [18240,200] x [4096,200]^T (fp32, decision-grade)
    {
        dim3 grid(T/64, LLM/64);
        gemm_nt_kernel<<<grid, 256>>>(ppe2, inp_w, inp_b, pproj, T, LLM, DM);
    }
    // table = codebook @ outp_w^T + outp_b : [4096,4096] x [200,4096]^T
    {
        dim3 grid(KC/64, (DM + 63)/64);
        gemm_nt_kernel<<<grid, 256>>>(cb, outp_w, outp_b, ptable, KC, DM, LLM);
    }
    cnorm_kernel<<<KC, 256>>>(cb, pcn, pcnd);

    // bf16 copies for the tensor-core coarse pass
    {
        size_t n4p = (size_t)T * LLM / 4;
        cvt_bf16_kernel<<<(int)((n4p + 255)/256), 256>>>(pproj, pprojh, n4p);
        size_t n4c = (size_t)KC * LLM / 4;
        cvt_bf16_kernel<<<(int)((n4c + 255)/256), 256>>>(cb, pcbh, n4c);
    }

    // dominant: pipelined mma.sync bf16 score GEMM + per-32-col-block top-2 candidates
    {
        dim3 grid(KC/128, TPAD/128);
        score_mma_kernel<<<grid, 256, SM_TOTAL>>>(pprojh, pcbh, pcn, pcand);
    }

    // exact decision: top-8 by coarse key, fp64 rescore, argmax (tie -> smaller index)
    refine8_kernel<<<T, 256>>>(pcand, pproj, cb, pcnd, pidx);

    // gather quantized output
    gather_kernel<<<(NOUT + 255)/256, 256>>>(pidx, ptable, out);
}